// round 11
// baseline (speedup 1.0000x reference)
#include <cuda_runtime.h>
#include <mma.h>
#include <cstdint>

using namespace nvcuda;

#define NNODES 50000
#define MPAD   50048
#define FDIM   128
#define KNB    32
#define EDIM   16
#define KK     2048          // FDIM * EDIM
#define KSPLIT 2
#define KHALF  (KK / KSPLIT) // 1024

__device__ float g_buf[(size_t)MPAD * KK];            // [i][l*16+n], pad rows stay 0
__device__ float W2[KK * FDIM];                       // [k=(l*16+n)][m]
__device__ float Cpart[KSPLIT][(size_t)MPAD * FDIM];  // split-K partials
__device__ int   g_nlist_is64;

// ---------------------------------------------------------------------------
__global__ void detect_nlist(const int* __restrict__ nl) {
    int odd_or = 0;
#pragma unroll
    for (int t = 1; t < 64; t += 2) odd_or |= nl[t];
    g_nlist_is64 = (odd_or == 0) ? 1 : 0;
}

// W2[(l*16+n)*128 + m] = tf32(w[l,m,n])
__global__ void build_w2(const float* __restrict__ w) {
    int idx = blockIdx.x * 256 + threadIdx.x;
    if (idx < KK * FDIM) {
        int m = idx & (FDIM - 1);
        int k = idx >> 7;
        int l = k >> 4;
        int n = k & (EDIM - 1);
        W2[idx] = wmma::__float_to_tf32(w[(size_t)l * FDIM * EDIM + (size_t)m * EDIM + n]);
    }
}

// ---------------------------------------------------------------------------
__device__ __forceinline__ void cp16(void* s, const void* g) {
    uint32_t sa = (uint32_t)__cvta_generic_to_shared(s);
    asm volatile("cp.async.cg.shared.global [%0], [%1], 16;\n" :: "r"(sa), "l"(g));
}
__device__ __forceinline__ void cp_commit() { asm volatile("cp.async.commit_group;\n"); }
template <int N>
__device__ __forceinline__ void cp_wait() { asm volatile("cp.async.wait_group %0;\n" :: "n"(N)); }

// ---------------------------------------------------------------------------
// Stage 1 (scalar fp32, exact):
//   g[i, l*16+n] = tf32_round( sum_j nodes[nlist[i,j], l] * edges[i,j,n] )
// ---------------------------------------------------------------------------
__global__ void gather_contract(const float* __restrict__ nodes,
                                const int* __restrict__ nlist32,
                                const float* __restrict__ edges) {
    int i = blockIdx.x;
    int l = threadIdx.x;  // 0..127

    __shared__ __align__(16) float se[KNB * EDIM];
    __shared__ int snb[KNB];

    ((float4*)se)[l] = ((const float4*)(edges + (size_t)i * KNB * EDIM))[l];
    if (l < KNB) {
        int pos = i * KNB + l;
        int idx = g_nlist_is64 ? nlist32[2 * (size_t)pos] : nlist32[pos];
        idx = idx < 0 ? 0 : (idx >= NNODES ? NNODES - 1 : idx);
        snb[l] = idx;
    }
    __syncthreads();

    float acc[EDIM];
#pragma unroll
    for (int n = 0; n < EDIM; n++) acc[n] = 0.f;

#pragma unroll 4
    for (int j = 0; j < KNB; j++) {
        float v = __ldg(nodes + (size_t)snb[j] * FDIM + l);
#pragma unroll
        for (int n = 0; n < EDIM; n++)
            acc[n] = fmaf(v, se[j * EDIM + n], acc[n]);
    }

    float4* g4 = (float4*)(g_buf + (size_t)i * KK + (size_t)l * EDIM);
#pragma unroll
    for (int q = 0; q < 4; q++) {
        g4[q] = make_float4(wmma::__float_to_tf32(acc[q * 4 + 0]),
                            wmma::__float_to_tf32(acc[q * 4 + 1]),
                            wmma::__float_to_tf32(acc[q * 4 + 2]),
                            wmma::__float_to_tf32(acc[q * 4 + 3]));
    }
}

// ---------------------------------------------------------------------------
// Stage 2: split-K tf32 wmma GEMM, 512 threads, 4x4 warp grid, warp tile 32x32.
// BM=128, BN=128, BK=32, 3-stage cp.async ring, 1 sync/iter, 32 iters.
// launch_bounds(512,2) -> <=64 regs -> 32 warps/SM (occ 50%).
// ---------------------------------------------------------------------------
#define BK2        32
#define STAGES     3
#define AS_STRIDE  36
#define AS_BYTES   (128 * AS_STRIDE * 4)       // 18432
#define BS_STRIDE  132
#define BS_BYTES   (BK2 * BS_STRIDE * 4)       // 16896
#define STAGE_BYTES (AS_BYTES + BS_BYTES)      // 35328
#define S2_SMEM    (STAGES * STAGE_BYTES)      // 105984

__global__ __launch_bounds__(512, 2) void gemm_tf32() {
    extern __shared__ __align__(16) char s2mem[];

    const int tid = threadIdx.x;
    const int wid = tid >> 5;
    const int warp_m = wid >> 2;   // 0..3 -> 32 rows
    const int warp_n = wid & 3;    // 0..3 -> 32 cols
    const size_t row0 = (size_t)blockIdx.x * 128;
    const int    koff = blockIdx.y * KHALF;
    float* Cp = &Cpart[blockIdx.y][0];

    auto Asm = [&](int s) -> float* { return (float*)(s2mem + s * STAGE_BYTES); };
    auto Bsm = [&](int s) -> float* { return (float*)(s2mem + s * STAGE_BYTES + AS_BYTES); };

    wmma::fragment<wmma::accumulator, 16, 16, 8, float> c[2][2];
#pragma unroll
    for (int mi = 0; mi < 2; mi++)
#pragma unroll
        for (int ni = 0; ni < 2; ni++) wmma::fill_fragment(c[mi][ni], 0.0f);

    auto load_tiles = [&](int s, int kb) {
        const float* Ab = g_buf + row0 * KK + (size_t)(koff + kb * BK2);
        const float* Bb = W2 + (size_t)(koff + kb * BK2) * FDIM;
        float* A = Asm(s);
        float* B = Bsm(s);
#pragma unroll
        for (int u = 0; u < 2; u++) {          // A: 128 x 32 -> 1024 float4
            int q = tid + u * 512;
            int ar = q >> 3, ac = q & 7;
            cp16(A + ar * AS_STRIDE + ac * 4, Ab + (size_t)ar * KK + ac * 4);
        }
#pragma unroll
        for (int u = 0; u < 2; u++) {          // B: 32 x 128 -> 1024 float4
            int q = tid + u * 512;
            int br = q >> 5, bc = q & 31;
            cp16(B + br * BS_STRIDE + bc * 4, Bb + br * FDIM + bc * 4);
        }
        cp_commit();
    };

    load_tiles(0, 0);
    load_tiles(1, 1);

    const int nkb = KHALF / BK2;  // 32
    for (int kb = 0; kb < nkb; kb++) {
        int cur = kb % STAGES;

        if (kb + 1 < nkb) cp_wait<1>();
        else              cp_wait<0>();
        __syncthreads();

        if (kb + 2 < nkb) load_tiles((kb + 2) % STAGES, kb + 2);

        const float* A = Asm(cur);
        const float* B = Bsm(cur);
#pragma unroll
        for (int kk = 0; kk < 4; kk++) {
            wmma::fragment<wmma::matrix_a, 16, 16, 8, wmma::precision::tf32, wmma::row_major> a[2];
            wmma::fragment<wmma::matrix_b, 16, 16, 8, wmma::precision::tf32, wmma::row_major> b[2];
#pragma unroll
            for (int mi = 0; mi < 2; mi++)
                wmma::load_matrix_sync(a[mi],
                    A + (warp_m * 32 + mi * 16) * AS_STRIDE + kk * 8, AS_STRIDE);
#pragma unroll
            for (int ni = 0; ni < 2; ni++)
                wmma::load_matrix_sync(b[ni],
                    B + (kk * 8) * BS_STRIDE + warp_n * 32 + ni * 16, BS_STRIDE);
#pragma unroll
            for (int mi = 0; mi < 2; mi++)
#pragma unroll
                for (int ni = 0; ni < 2; ni++)
                    wmma::mma_sync(c[mi][ni], a[mi], b[ni], c[mi][ni]);
        }
    }

#pragma unroll
    for (int mi = 0; mi < 2; mi++)
#pragma unroll
        for (int ni = 0; ni < 2; ni++) {
            size_t rglob = row0 + warp_m * 32 + mi * 16;
            if (rglob < NNODES)   // 16-row fragments fully valid (80 % 16 == 0)
                wmma::store_matrix_sync(Cp + rglob * FDIM + warp_n * 32 + ni * 16,
                                        c[mi][ni], FDIM, wmma::mem_row_major);
        }
}

// ---------------------------------------------------------------------------
// Reduce: out = (Cpart0 + Cpart1) / 32   (valid rows only), float4.
// ---------------------------------------------------------------------------
__global__ void reduce_out(float* __restrict__ out) {
    size_t i = (size_t)blockIdx.x * 256 + threadIdx.x;
    if (i < (size_t)NNODES * FDIM / 4) {
        float4 a = ((const float4*)&Cpart[0][0])[i];
        float4 b = ((const float4*)&Cpart[1][0])[i];
        const float s = 1.0f / (float)KNB;
        ((float4*)out)[i] = make_float4((a.x + b.x) * s, (a.y + b.y) * s,
                                        (a.z + b.z) * s, (a.w + b.w) * s);
    }
}

// ---------------------------------------------------------------------------
extern "C" void kernel_launch(void* const* d_in, const int* in_sizes, int n_in,
                              void* d_out, int out_size) {
    const float* nodes = nullptr;
    const int*   nlist = nullptr;
    const float* edges = nullptr;
    const float* w     = nullptr;
    for (int t = 0; t < n_in; t++) {
        long long s = in_sizes[t];
        if      (s == (long long)NNODES * FDIM)        nodes = (const float*)d_in[t];
        else if (s == (long long)NNODES * KNB)         nlist = (const int*)d_in[t];
        else if (s == (long long)NNODES * KNB * EDIM)  edges = (const float*)d_in[t];
        else if (s == (long long)FDIM * FDIM * EDIM)   w     = (const float*)d_in[t];
    }
    if (!nodes) nodes = (const float*)d_in[0];
    if (!nlist) nlist = (const int*)d_in[1];
    if (!edges) edges = (const float*)d_in[2];
    if (!w)     w     = (const float*)d_in[3];

    float* out = (float*)d_out;

    static bool attr_done = false;
    if (!attr_done) {
        cudaFuncSetAttribute(gemm_tf32,
                             cudaFuncAttributeMaxDynamicSharedMemorySize, S2_SMEM);
        attr_done = true;
    }

    detect_nlist<<<1, 1>>>(nlist);
    build_w2<<<(KK * FDIM + 255) / 256, 256>>>(w);
    gather_contract<<<NNODES, FDIM>>>(nodes, nlist, edges);
    gemm_tf32<<<dim3(MPAD / 128, KSPLIT), 512, S2_SMEM>>>();
    reduce_out<<<((NNODES * FDIM / 4) + 255) / 256, 256>>>(out);
}

// round 13
// speedup vs baseline: 1.0758x; 1.0758x over previous
#include <cuda_runtime.h>
#include <mma.h>
#include <cstdint>

using namespace nvcuda;

#define NNODES 50000
#define MPAD   50048
#define FDIM   128
#define KNB    32
#define EDIM   16
#define KK     2048          // FDIM * EDIM
#define KSPLIT 2
#define KHALF  (KK / KSPLIT) // 1024

__device__ float g_buf[(size_t)MPAD * KK];            // [i][l*16+n], pad rows stay 0
__device__ float W2[KK * FDIM];                       // [k=(l*16+n)][m]
__device__ float Cpart[KSPLIT][(size_t)MPAD * FDIM];  // split-K partials
__device__ int   g_nlist_is64;

// ---------------------------------------------------------------------------
__global__ void detect_nlist(const int* __restrict__ nl) {
    int odd_or = 0;
#pragma unroll
    for (int t = 1; t < 64; t += 2) odd_or |= nl[t];
    g_nlist_is64 = (odd_or == 0) ? 1 : 0;
}

// W2[(l*16+n)*128 + m] = tf32(w[l,m,n])
__global__ void build_w2(const float* __restrict__ w) {
    int idx = blockIdx.x * 256 + threadIdx.x;
    if (idx < KK * FDIM) {
        int m = idx & (FDIM - 1);
        int k = idx >> 7;
        int l = k >> 4;
        int n = k & (EDIM - 1);
        W2[idx] = wmma::__float_to_tf32(w[(size_t)l * FDIM * EDIM + (size_t)m * EDIM + n]);
    }
}

// ---------------------------------------------------------------------------
__device__ __forceinline__ void cp16(void* s, const void* g) {
    uint32_t sa = (uint32_t)__cvta_generic_to_shared(s);
    asm volatile("cp.async.cg.shared.global [%0], [%1], 16;\n" :: "r"(sa), "l"(g));
}
__device__ __forceinline__ void cp_commit() { asm volatile("cp.async.commit_group;\n"); }
template <int N>
__device__ __forceinline__ void cp_wait() { asm volatile("cp.async.wait_group %0;\n" :: "n"(N)); }

// ---------------------------------------------------------------------------
// Stage 1 (packed f32x2 FFMA2, fp32-exact):
//   g[i, l*16+n] = tf32_round( sum_j nodes[nlist[i,j], l] * edges[i,j,n] )
// One CTA per node, 128 threads (thread = l). 16 n-accumulators packed as
// 8 f32x2 chains: 8 FFMA2 + 8 broadcast LDS.64 per neighbor (vs 16 + 16).
// ---------------------------------------------------------------------------
__global__ void gather_contract(const float* __restrict__ nodes,
                                const int* __restrict__ nlist32,
                                const float* __restrict__ edges) {
    int i = blockIdx.x;
    int l = threadIdx.x;  // 0..127

    __shared__ __align__(16) float se[KNB * EDIM];  // 512 floats
    __shared__ int snb[KNB];

    ((float4*)se)[l] = ((const float4*)(edges + (size_t)i * KNB * EDIM))[l];
    if (l < KNB) {
        int pos = i * KNB + l;
        int idx = g_nlist_is64 ? nlist32[2 * (size_t)pos] : nlist32[pos];
        idx = idx < 0 ? 0 : (idx >= NNODES ? NNODES - 1 : idx);
        snb[l] = idx;
    }
    __syncthreads();

    unsigned long long acc2[8];
#pragma unroll
    for (int q = 0; q < 8; q++) acc2[q] = 0ULL;

    const unsigned long long* se2 = (const unsigned long long*)se;  // f32x2 pairs

#pragma unroll 4
    for (int j = 0; j < KNB; j++) {
        float v = __ldg(nodes + (size_t)snb[j] * FDIM + l);
        unsigned long long vv;
        asm("mov.b64 %0, {%1, %1};" : "=l"(vv) : "f"(v));
#pragma unroll
        for (int q = 0; q < 8; q++) {
            asm("fma.rn.f32x2 %0, %1, %2, %3;"
                : "=l"(acc2[q]) : "l"(vv), "l"(se2[j * 8 + q]), "l"(acc2[q]));
        }
    }

    // unpack, round to tf32, store coalesced
    float accf[16];
#pragma unroll
    for (int q = 0; q < 8; q++) {
        float lo, hi;
        asm("mov.b64 {%0, %1}, %2;" : "=f"(lo), "=f"(hi) : "l"(acc2[q]));
        accf[2 * q]     = wmma::__float_to_tf32(lo);
        accf[2 * q + 1] = wmma::__float_to_tf32(hi);
    }
    float4* g4 = (float4*)(g_buf + (size_t)i * KK + (size_t)l * EDIM);
#pragma unroll
    for (int q = 0; q < 4; q++)
        g4[q] = make_float4(accf[q * 4 + 0], accf[q * 4 + 1],
                            accf[q * 4 + 2], accf[q * 4 + 3]);
}

// ---------------------------------------------------------------------------
// Stage 2: split-K tf32 wmma GEMM (R10 config: 256 thr, warp tile 32x64).
// BM=128, BN=128, BK=32, 3-stage cp.async ring, 1 sync/iter, 32 iters.
// ---------------------------------------------------------------------------
#define BK2        32
#define STAGES     3
#define AS_STRIDE  36
#define AS_BYTES   (128 * AS_STRIDE * 4)       // 18432
#define BS_STRIDE  132
#define BS_BYTES   (BK2 * BS_STRIDE * 4)       // 16896
#define STAGE_BYTES (AS_BYTES + BS_BYTES)      // 35328
#define S2_SMEM    (STAGES * STAGE_BYTES)      // 105984

__global__ __launch_bounds__(256, 2) void gemm_tf32() {
    extern __shared__ __align__(16) char s2mem[];

    const int tid = threadIdx.x;
    const int wid = tid >> 5;
    const int warp_m = wid >> 1;   // 0..3
    const int warp_n = wid & 1;    // 0..1
    const size_t row0 = (size_t)blockIdx.x * 128;
    const int    koff = blockIdx.y * KHALF;
    float* Cp = &Cpart[blockIdx.y][0];

    auto Asm = [&](int s) -> float* { return (float*)(s2mem + s * STAGE_BYTES); };
    auto Bsm = [&](int s) -> float* { return (float*)(s2mem + s * STAGE_BYTES + AS_BYTES); };

    wmma::fragment<wmma::accumulator, 16, 16, 8, float> c[2][4];
#pragma unroll
    for (int mi = 0; mi < 2; mi++)
#pragma unroll
        for (int ni = 0; ni < 4; ni++) wmma::fill_fragment(c[mi][ni], 0.0f);

    auto load_tiles = [&](int s, int kb) {
        const float* Ab = g_buf + row0 * KK + (size_t)(koff + kb * BK2);
        const float* Bb = W2 + (size_t)(koff + kb * BK2) * FDIM;
        float* A = Asm(s);
        float* B = Bsm(s);
#pragma unroll
        for (int u = 0; u < 4; u++) {          // A: 128 x 32 -> 1024 float4
            int q = tid + u * 256;
            int ar = q >> 3, ac = q & 7;
            cp16(A + ar * AS_STRIDE + ac * 4, Ab + (size_t)ar * KK + ac * 4);
        }
#pragma unroll
        for (int u = 0; u < 4; u++) {          // B: 32 x 128 -> 1024 float4
            int q = tid + u * 256;
            int br = q >> 5, bc = q & 31;
            cp16(B + br * BS_STRIDE + bc * 4, Bb + br * FDIM + bc * 4);
        }
        cp_commit();
    };

    load_tiles(0, 0);
    load_tiles(1, 1);

    const int nkb = KHALF / BK2;  // 32
    for (int kb = 0; kb < nkb; kb++) {
        int cur = kb % STAGES;

        if (kb + 1 < nkb) cp_wait<1>();
        else              cp_wait<0>();
        __syncthreads();

        if (kb + 2 < nkb) load_tiles((kb + 2) % STAGES, kb + 2);

        const float* A = Asm(cur);
        const float* B = Bsm(cur);
#pragma unroll
        for (int kk = 0; kk < 4; kk++) {
            wmma::fragment<wmma::matrix_a, 16, 16, 8, wmma::precision::tf32, wmma::row_major> a[2];
            wmma::fragment<wmma::matrix_b, 16, 16, 8, wmma::precision::tf32, wmma::row_major> b[4];
#pragma unroll
            for (int mi = 0; mi < 2; mi++)
                wmma::load_matrix_sync(a[mi],
                    A + (warp_m * 32 + mi * 16) * AS_STRIDE + kk * 8, AS_STRIDE);
#pragma unroll
            for (int ni = 0; ni < 4; ni++)
                wmma::load_matrix_sync(b[ni],
                    B + (kk * 8) * BS_STRIDE + warp_n * 64 + ni * 16, BS_STRIDE);
#pragma unroll
            for (int mi = 0; mi < 2; mi++)
#pragma unroll
                for (int ni = 0; ni < 4; ni++)
                    wmma::mma_sync(c[mi][ni], a[mi], b[ni], c[mi][ni]);
        }
    }

#pragma unroll
    for (int mi = 0; mi < 2; mi++)
#pragma unroll
        for (int ni = 0; ni < 4; ni++) {
            size_t rglob = row0 + warp_m * 32 + mi * 16;
            if (rglob < NNODES)   // 16-row fragments fully valid (80 % 16 == 0)
                wmma::store_matrix_sync(Cp + rglob * FDIM + warp_n * 64 + ni * 16,
                                        c[mi][ni], FDIM, wmma::mem_row_major);
        }
}

// ---------------------------------------------------------------------------
// Reduce: out = (Cpart0 + Cpart1) / 32   (valid rows only), float4.
// ---------------------------------------------------------------------------
__global__ void reduce_out(float* __restrict__ out) {
    size_t i = (size_t)blockIdx.x * 256 + threadIdx.x;
    if (i < (size_t)NNODES * FDIM / 4) {
        float4 a = ((const float4*)&Cpart[0][0])[i];
        float4 b = ((const float4*)&Cpart[1][0])[i];
        const float s = 1.0f / (float)KNB;
        ((float4*)out)[i] = make_float4((a.x + b.x) * s, (a.y + b.y) * s,
                                        (a.z + b.z) * s, (a.w + b.w) * s);
    }
}

// ---------------------------------------------------------------------------
extern "C" void kernel_launch(void* const* d_in, const int* in_sizes, int n_in,
                              void* d_out, int out_size) {
    const float* nodes = nullptr;
    const int*   nlist = nullptr;
    const float* edges = nullptr;
    const float* w     = nullptr;
    for (int t = 0; t < n_in; t++) {
        long long s = in_sizes[t];
        if      (s == (long long)NNODES * FDIM)        nodes = (const float*)d_in[t];
        else if (s == (long long)NNODES * KNB)         nlist = (const int*)d_in[t];
        else if (s == (long long)NNODES * KNB * EDIM)  edges = (const float*)d_in[t];
        else if (s == (long long)FDIM * FDIM * EDIM)   w     = (const float*)d_in[t];
    }
    if (!nodes) nodes = (const float*)d_in[0];
    if (!nlist) nlist = (const int*)d_in[1];
    if (!edges) edges = (const float*)d_in[2];
    if (!w)     w     = (const float*)d_in[3];

    float* out = (float*)d_out;

    static bool attr_done = false;
    if (!attr_done) {
        cudaFuncSetAttribute(gemm_tf32,
                             cudaFuncAttributeMaxDynamicSharedMemorySize, S2_SMEM);
        attr_done = true;
    }

    detect_nlist<<<1, 1>>>(nlist);
    build_w2<<<(KK * FDIM + 255) / 256, 256>>>(w);
    gather_contract<<<NNODES, FDIM>>>(nodes, nlist, edges);
    gemm_tf32<<<dim3(MPAD / 128, KSPLIT), 256, S2_SMEM>>>();
    reduce_out<<<((NNODES * FDIM / 4) + 255) / 256, 256>>>(out);
}

// round 14
// speedup vs baseline: 1.1047x; 1.0269x over previous
#include <cuda_runtime.h>
#include <mma.h>
#include <cstdint>

using namespace nvcuda;

#define NNODES 50000
#define MPAD   50048
#define FDIM   128
#define KNB    32
#define EDIM   16
#define KK     2048          // FDIM * EDIM

__device__ float g_buf[(size_t)MPAD * KK];   // [i][l*16+n], pad rows stay 0
__device__ float W2[KK * FDIM];              // [k=(l*16+n)][m]
__device__ int   g_nlist_is64;

// ---------------------------------------------------------------------------
__global__ void detect_nlist(const int* __restrict__ nl) {
    int odd_or = 0;
#pragma unroll
    for (int t = 1; t < 64; t += 2) odd_or |= nl[t];
    g_nlist_is64 = (odd_or == 0) ? 1 : 0;
}

// W2[(l*16+n)*128 + m] = tf32(w[l,m,n])
__global__ void build_w2(const float* __restrict__ w) {
    int idx = blockIdx.x * 256 + threadIdx.x;
    if (idx < KK * FDIM) {
        int m = idx & (FDIM - 1);
        int k = idx >> 7;
        int l = k >> 4;
        int n = k & (EDIM - 1);
        W2[idx] = wmma::__float_to_tf32(w[(size_t)l * FDIM * EDIM + (size_t)m * EDIM + n]);
    }
}

// ---------------------------------------------------------------------------
__device__ __forceinline__ void cp16(void* s, const void* g) {
    uint32_t sa = (uint32_t)__cvta_generic_to_shared(s);
    asm volatile("cp.async.cg.shared.global [%0], [%1], 16;\n" :: "r"(sa), "l"(g));
}
__device__ __forceinline__ void cp_commit() { asm volatile("cp.async.commit_group;\n"); }
template <int N>
__device__ __forceinline__ void cp_wait() { asm volatile("cp.async.wait_group %0;\n" :: "n"(N)); }

// ---------------------------------------------------------------------------
// Stage 1 (FFMA2 + vectorized smem): per node i, thread l:
//   g[i, l*16+n] = tf32_rn( sum_j nodes[nlist[i,j], l] * edges[i,j,n] )
// Per neighbor: 1 LDG + 4 ld.shared.v2.u64 (broadcast) + 8 fma.rn.f32x2.
// ---------------------------------------------------------------------------
__global__ void gather_contract(const float* __restrict__ nodes,
                                const int* __restrict__ nlist32,
                                const float* __restrict__ edges) {
    int i = blockIdx.x;
    int l = threadIdx.x;  // 0..127

    __shared__ __align__(16) float se[KNB * EDIM];  // 512 floats
    __shared__ int snb[KNB];

    ((float4*)se)[l] = ((const float4*)(edges + (size_t)i * KNB * EDIM))[l];
    if (l < KNB) {
        int pos = i * KNB + l;
        int idx = g_nlist_is64 ? nlist32[2 * (size_t)pos] : nlist32[pos];
        idx = idx < 0 ? 0 : (idx >= NNODES ? NNODES - 1 : idx);
        snb[l] = idx;
    }
    __syncthreads();

    unsigned long long acc2[8];
#pragma unroll
    for (int q = 0; q < 8; q++) acc2[q] = 0ULL;

    const uint32_t se_base = (uint32_t)__cvta_generic_to_shared(se);

#pragma unroll 4
    for (int j = 0; j < KNB; j++) {
        float v = __ldg(nodes + (size_t)snb[j] * FDIM + l);
        unsigned long long vv;
        asm("mov.b64 %0, {%1, %1};" : "=l"(vv) : "f"(v));
        uint32_t ja = se_base + j * (EDIM * 4);
#pragma unroll
        for (int q = 0; q < 4; q++) {
            unsigned long long e0, e1;
            asm("ld.shared.v2.u64 {%0, %1}, [%2];"
                : "=l"(e0), "=l"(e1) : "r"(ja + q * 16));
            asm("fma.rn.f32x2 %0, %1, %2, %3;"
                : "=l"(acc2[2 * q])     : "l"(vv), "l"(e0), "l"(acc2[2 * q]));
            asm("fma.rn.f32x2 %0, %1, %2, %3;"
                : "=l"(acc2[2 * q + 1]) : "l"(vv), "l"(e1), "l"(acc2[2 * q + 1]));
        }
    }

    // unpack, round to tf32, store coalesced
    float accf[16];
#pragma unroll
    for (int q = 0; q < 8; q++) {
        float lo, hi;
        asm("mov.b64 {%0, %1}, %2;" : "=f"(lo), "=f"(hi) : "l"(acc2[q]));
        accf[2 * q]     = wmma::__float_to_tf32(lo);
        accf[2 * q + 1] = wmma::__float_to_tf32(hi);
    }
    float4* g4 = (float4*)(g_buf + (size_t)i * KK + (size_t)l * EDIM);
#pragma unroll
    for (int q = 0; q < 4; q++)
        g4[q] = make_float4(accf[q * 4 + 0], accf[q * 4 + 1],
                            accf[q * 4 + 2], accf[q * 4 + 3]);
}

// ---------------------------------------------------------------------------
// Stage 2: C = (1/32) * g_buf @ W2  (M=50048, N=128, K=2048), tf32 wmma.
// BM=128, BN=128, BK=32, 3-stage cp.async ring, 1 sync/iter, 64 iters.
// Epilogue scales and stores directly to out (fragment-predicated tail).
// ---------------------------------------------------------------------------
#define BK2        32
#define STAGES     3
#define AS_STRIDE  36
#define AS_BYTES   (128 * AS_STRIDE * 4)       // 18432
#define BS_STRIDE  132
#define BS_BYTES   (BK2 * BS_STRIDE * 4)       // 16896
#define STAGE_BYTES (AS_BYTES + BS_BYTES)      // 35328
#define S2_SMEM    (STAGES * STAGE_BYTES)      // 105984

__global__ __launch_bounds__(256, 2) void gemm_tf32(float* __restrict__ out) {
    extern __shared__ __align__(16) char s2mem[];

    const int tid = threadIdx.x;
    const int wid = tid >> 5;
    const int warp_m = wid >> 1;   // 0..3
    const int warp_n = wid & 1;    // 0..1
    const size_t row0 = (size_t)blockIdx.x * 128;

    auto Asm = [&](int s) -> float* { return (float*)(s2mem + s * STAGE_BYTES); };
    auto Bsm = [&](int s) -> float* { return (float*)(s2mem + s * STAGE_BYTES + AS_BYTES); };

    wmma::fragment<wmma::accumulator, 16, 16, 8, float> c[2][4];
#pragma unroll
    for (int mi = 0; mi < 2; mi++)
#pragma unroll
        for (int ni = 0; ni < 4; ni++) wmma::fill_fragment(c[mi][ni], 0.0f);

    auto load_tiles = [&](int s, int kb) {
        const float* Ab = g_buf + row0 * KK + (size_t)(kb * BK2);
        const float* Bb = W2 + (size_t)(kb * BK2) * FDIM;
        float* A = Asm(s);
        float* B = Bsm(s);
#pragma unroll
        for (int u = 0; u < 4; u++) {          // A: 128 x 32 -> 1024 float4
            int q = tid + u * 256;
            int ar = q >> 3, ac = q & 7;
            cp16(A + ar * AS_STRIDE + ac * 4, Ab + (size_t)ar * KK + ac * 4);
        }
#pragma unroll
        for (int u = 0; u < 4; u++) {          // B: 32 x 128 -> 1024 float4
            int q = tid + u * 256;
            int br = q >> 5, bc = q & 31;
            cp16(B + br * BS_STRIDE + bc * 4, Bb + br * FDIM + bc * 4);
        }
        cp_commit();
    };

    load_tiles(0, 0);
    load_tiles(1, 1);

    const int nkb = KK / BK2;  // 64
    for (int kb = 0; kb < nkb; kb++) {
        int cur = kb % STAGES;

        if (kb + 1 < nkb) cp_wait<1>();
        else              cp_wait<0>();
        __syncthreads();

        if (kb + 2 < nkb) load_tiles((kb + 2) % STAGES, kb + 2);

        const float* A = Asm(cur);
        const float* B = Bsm(cur);
#pragma unroll
        for (int kk = 0; kk < 4; kk++) {
            wmma::fragment<wmma::matrix_a, 16, 16, 8, wmma::precision::tf32, wmma::row_major> a[2];
            wmma::fragment<wmma::matrix_b, 16, 16, 8, wmma::precision::tf32, wmma::row_major> b[4];
#pragma unroll
            for (int mi = 0; mi < 2; mi++)
                wmma::load_matrix_sync(a[mi],
                    A + (warp_m * 32 + mi * 16) * AS_STRIDE + kk * 8, AS_STRIDE);
#pragma unroll
            for (int ni = 0; ni < 4; ni++)
                wmma::load_matrix_sync(b[ni],
                    B + (kk * 8) * BS_STRIDE + warp_n * 64 + ni * 16, BS_STRIDE);
#pragma unroll
            for (int mi = 0; mi < 2; mi++)
#pragma unroll
                for (int ni = 0; ni < 4; ni++)
                    wmma::mma_sync(c[mi][ni], a[mi], b[ni], c[mi][ni]);
        }
    }

    const float scale = 1.0f / (float)KNB;
#pragma unroll
    for (int mi = 0; mi < 2; mi++)
#pragma unroll
        for (int ni = 0; ni < 4; ni++) {
#pragma unroll
            for (int t = 0; t < c[mi][ni].num_elements; t++) c[mi][ni].x[t] *= scale;
            size_t rglob = row0 + warp_m * 32 + mi * 16;
            if (rglob < NNODES)   // 16-row fragments fully valid (80 % 16 == 0)
                wmma::store_matrix_sync(out + rglob * FDIM + warp_n * 64 + ni * 16,
                                        c[mi][ni], FDIM, wmma::mem_row_major);
        }
}

// ---------------------------------------------------------------------------
extern "C" void kernel_launch(void* const* d_in, const int* in_sizes, int n_in,
                              void* d_out, int out_size) {
    const float* nodes = nullptr;
    const int*   nlist = nullptr;
    const float* edges = nullptr;
    const float* w     = nullptr;
    for (int t = 0; t < n_in; t++) {
        long long s = in_sizes[t];
        if      (s == (long long)NNODES * FDIM)        nodes = (const float*)d_in[t];
        else if (s == (long long)NNODES * KNB)         nlist = (const int*)d_in[t];
        else if (s == (long long)NNODES * KNB * EDIM)  edges = (const float*)d_in[t];
        else if (s == (long long)FDIM * FDIM * EDIM)   w     = (const float*)d_in[t];
    }
    if (!nodes) nodes = (const float*)d_in[0];
    if (!nlist) nlist = (const int*)d_in[1];
    if (!edges) edges = (const float*)d_in[2];
    if (!w)     w     = (const float*)d_in[3];

    float* out = (float*)d_out;

    static bool attr_done = false;
    if (!attr_done) {
        cudaFuncSetAttribute(gemm_tf32,
                             cudaFuncAttributeMaxDynamicSharedMemorySize, S2_SMEM);
        attr_done = true;
    }

    detect_nlist<<<1, 1>>>(nlist);
    build_w2<<<(KK * FDIM + 255) / 256, 256>>>(w);
    gather_contract<<<NNODES, FDIM>>>(nodes, nlist, edges);
    gemm_tf32<<<MPAD / 128, 256, S2_SMEM>>>(out);
}